// round 3
// baseline (speedup 1.0000x reference)
#include <cuda_runtime.h>
#include <math.h>

// Problem dims
#define NTOK 32768
#define ADIM 6
#define HDIM 1024
#define DDIM 128
#define KCB  4096

#define VQ_BLOCKS (NTOK / 64)

// Output layout (float32, concatenated in reference-return order)
#define OUT_INDS 0
#define OUT_Q    (NTOK)                       // 32768
#define OUT_REC  (NTOK + NTOK * DDIM)         // 4227072
#define OUT_LOSS (NTOK + NTOK * DDIM + NTOK * ADIM)  // 4423680

// -------- scratch (device globals; no runtime allocation) --------
__device__ float g_h1[NTOK * HDIM];     // 134 MB
__device__ float g_h2[NTOK * HDIM];     // 134 MB
__device__ float g_lat[NTOK * DDIM];    // 16.7 MB
__device__ float g_q[NTOK * DDIM];      // 16.7 MB
__device__ float g_ln[NTOK];            // ||latents||^2 per row
__device__ float g_cn[KCB];
__device__ float g_part[VQ_BLOCKS];

// ---------------------------------------------------------------------------
// XLA-style row sum-of-squares: warp per row, lane-strided, NO fma contraction,
// shfl_down tree (16,8,4,2,1). Matches XLA reduce(mul(x,x)) emission.
// ---------------------------------------------------------------------------
__device__ __forceinline__ float row_sumsq_128(const float* __restrict__ row, int lane)
{
    float acc = 0.f;
#pragma unroll
    for (int i = 0; i < 4; i++) {
        float v = row[lane + i * 32];
        float e = __fmul_rn(v, v);
        acc = __fadd_rn(acc, e);
    }
#pragma unroll
    for (int off = 16; off >= 1; off >>= 1)
        acc = __fadd_rn(acc, __shfl_down_sync(0xffffffffu, acc, off));
    return acc;   // valid in lane 0
}

__global__ void k_cnorm(const float* __restrict__ cb, float* __restrict__ cn)
{
    int w = (blockIdx.x * blockDim.x + threadIdx.x) >> 5;
    int lane = threadIdx.x & 31;
    float s = row_sumsq_128(cb + w * DDIM, lane);
    if (lane == 0) cn[w] = s;
}

__global__ void k_rownorm(const float* __restrict__ lat, float* __restrict__ ln)
{
    int w = (blockIdx.x * blockDim.x + threadIdx.x) >> 5;
    int lane = threadIdx.x & 31;
    float s = row_sumsq_128(lat + w * DDIM, lane);
    if (lane == 0) ln[w] = s;
}

// ---------------------------------------------------------------------------
// Encoder layer 1: h1 = relu(action @ W1 + b1), A=6.
// GEMM-order arithmetic: FMA chain from 0 over k ascending, bias LAST, relu.
// ---------------------------------------------------------------------------
__global__ void k_enc1(const float* __restrict__ act, const float* __restrict__ W1,
                       const float* __restrict__ b1, float* __restrict__ h1)
{
    int gid = blockIdx.x * blockDim.x + threadIdx.x;     // NTOK*HDIM threads
    int n = gid >> 10;
    int h = gid & 1023;
    const float* a = act + n * ADIM;
    float s = 0.f;
    s = __fmaf_rn(a[0], W1[0 * HDIM + h], s);
    s = __fmaf_rn(a[1], W1[1 * HDIM + h], s);
    s = __fmaf_rn(a[2], W1[2 * HDIM + h], s);
    s = __fmaf_rn(a[3], W1[3 * HDIM + h], s);
    s = __fmaf_rn(a[4], W1[4 * HDIM + h], s);
    s = __fmaf_rn(a[5], W1[5 * HDIM + h], s);
    s = __fadd_rn(s, b1[h]);
    h1[gid] = fmaxf(s, 0.f);
}

// ---------------------------------------------------------------------------
// SGEMM: C[M,Nn] = act( A[M,K] @ B[K,Nn] + bias ), tiles 128x128x8, 8x8/thread.
// Per-output accumulation: single accumulator, k ascending, FFMA — the same
// arithmetic chain as cuBLAS fp32 sgemm (bit-exact hypothesis).
// ---------------------------------------------------------------------------
template <int RELU>
__global__ __launch_bounds__(256)
void sgemm(const float* __restrict__ Am, const float* __restrict__ Bm,
           const float* __restrict__ bias, float* __restrict__ Cm,
           int M, int Nn, int Kk)
{
    __shared__ float As[8][128];
    __shared__ float Bs[8][128];

    int tid = threadIdx.x;
    int tx = tid & 15;          // 0..15 -> 8 cols each
    int ty = tid >> 4;          // 0..15 -> 8 rows each
    int mb = blockIdx.y * 128;
    int nb = blockIdx.x * 128;

    int arow = tid >> 1;            // 0..127
    int acol = (tid & 1) * 4;       // 0 or 4
    int brow = tid >> 5;            // 0..7
    int bcol = (tid & 31) * 4;      // 0..124

    const float* Aptr = Am + (mb + arow) * Kk + acol;
    const float* Bptr = Bm + brow * Nn + nb + bcol;

    float acc[8][8];
#pragma unroll
    for (int i = 0; i < 8; i++)
#pragma unroll
        for (int j = 0; j < 8; j++) acc[i][j] = 0.f;

    for (int k0 = 0; k0 < Kk; k0 += 8) {
        float4 av = *(const float4*)Aptr;
        As[acol + 0][arow] = av.x;
        As[acol + 1][arow] = av.y;
        As[acol + 2][arow] = av.z;
        As[acol + 3][arow] = av.w;
        *(float4*)&Bs[brow][bcol] = *(const float4*)Bptr;
        __syncthreads();

#pragma unroll
        for (int kk = 0; kk < 8; kk++) {
            float4 a0 = *(const float4*)&As[kk][ty * 8];
            float4 a1 = *(const float4*)&As[kk][ty * 8 + 4];
            float4 b0 = *(const float4*)&Bs[kk][tx * 8];
            float4 b1 = *(const float4*)&Bs[kk][tx * 8 + 4];
            float av8[8] = {a0.x, a0.y, a0.z, a0.w, a1.x, a1.y, a1.z, a1.w};
            float bv8[8] = {b0.x, b0.y, b0.z, b0.w, b1.x, b1.y, b1.z, b1.w};
#pragma unroll
            for (int i = 0; i < 8; i++)
#pragma unroll
                for (int j = 0; j < 8; j++)
                    acc[i][j] = __fmaf_rn(av8[i], bv8[j], acc[i][j]);
        }
        __syncthreads();
        Aptr += 8;
        Bptr += 8 * Nn;
    }

#pragma unroll
    for (int i = 0; i < 8; i++) {
        int row = mb + ty * 8 + i;
        float* Crow = Cm + row * Nn + nb + tx * 8;
        const float* brow2 = bias + nb + tx * 8;
#pragma unroll
        for (int j = 0; j < 8; j++) {
            float v = __fadd_rn(acc[i][j], brow2[j]);
            if (RELU) v = fmaxf(v, 0.f);
            Crow[j] = v;
        }
    }
}

// ---------------------------------------------------------------------------
// VQ kernel: 64 latent rows per block vs all 4096 codes.
// dist_k = fl( fl(L_n + C_k) - 2*dot ) — replicates the reference's fp32
// rounding so sub-ulp tie rows resolve identically (lowest index on equality).
// ---------------------------------------------------------------------------
__global__ __launch_bounds__(256)
void k_vq(const float* __restrict__ lat, const float* __restrict__ cb,
          const float* __restrict__ cn, const float* __restrict__ ln,
          float* __restrict__ out, float* __restrict__ gq,
          float* __restrict__ part)
{
    __shared__ float Ls[DDIM][68];   // latents tile transposed [d][row], padded
    __shared__ float Cs[8][68];      // code chunk transposed [d][code]
    __shared__ int s_ind[64];
    __shared__ float s_red[256];

    int tid = threadIdx.x;
    int tx = tid & 15;   // codes: 4 each
    int ty = tid >> 4;   // rows:  4 each
    int m0 = blockIdx.x * 64;

    // Load 64x128 latent tile (transposed into smem)
#pragma unroll
    for (int i = 0; i < 8; i++) {
        int e = tid + i * 256;         // float4 index over 2048
        int r = e >> 5;                // 32 float4 per row
        int d4 = (e & 31) * 4;
        float4 v = *(const float4*)(lat + (m0 + r) * DDIM + d4);
        Ls[d4 + 0][r] = v.x;
        Ls[d4 + 1][r] = v.y;
        Ls[d4 + 2][r] = v.z;
        Ls[d4 + 3][r] = v.w;
    }
    __syncthreads();

    // per-row ||l||^2 for the 4 rows this thread owns
    float Lrow[4];
#pragma unroll
    for (int i = 0; i < 4; i++) Lrow[i] = ln[m0 + ty * 4 + i];

    float bestv[4];
    int besti[4];
#pragma unroll
    for (int i = 0; i < 4; i++) { bestv[i] = 3.4e38f; besti[i] = 0; }

    for (int kt = 0; kt < KCB / 64; kt++) {
        int kc = kt * 64;
        float acc[4][4];
#pragma unroll
        for (int i = 0; i < 4; i++)
#pragma unroll
            for (int j = 0; j < 4; j++) acc[i][j] = 0.f;

        for (int dc = 0; dc < 16; dc++) {
            int d0 = dc * 8;
            if (tid < 128) {
                int code = tid >> 1;
                int dd0 = (tid & 1) * 4;
                float4 v = *(const float4*)(cb + (kc + code) * DDIM + d0 + dd0);
                Cs[dd0 + 0][code] = v.x;
                Cs[dd0 + 1][code] = v.y;
                Cs[dd0 + 2][code] = v.z;
                Cs[dd0 + 3][code] = v.w;
            }
            __syncthreads();
#pragma unroll
            for (int dd = 0; dd < 8; dd++) {
                float4 l = *(const float4*)&Ls[d0 + dd][ty * 4];
                float4 c = *(const float4*)&Cs[dd][tx * 4];
                float lv[4] = {l.x, l.y, l.z, l.w};
                float cv[4] = {c.x, c.y, c.z, c.w};
#pragma unroll
                for (int i = 0; i < 4; i++)
#pragma unroll
                    for (int j = 0; j < 4; j++)
                        acc[i][j] = __fmaf_rn(lv[i], cv[j], acc[i][j]);
            }
            __syncthreads();
        }

        // argmin update with reference-rounded distance; ascending scan keeps
        // first (lowest) index on exact fp32 equality.
#pragma unroll
        for (int j = 0; j < 4; j++) {
            int code = kc + tx * 4 + j;
            float cnv = cn[code];
#pragma unroll
            for (int i = 0; i < 4; i++) {
                float t = __fadd_rn(Lrow[i], cnv);            // fl(L + C)
                float dist = __fsub_rn(t, __fmul_rn(2.f, acc[i][j])); // fl(. - 2dot)
                if (dist < bestv[i]) { bestv[i] = dist; besti[i] = code; }
            }
        }
    }

    // Reduce across the 16 threads (tx) sharing each row; lower index on tie
#pragma unroll
    for (int i = 0; i < 4; i++) {
        float v = bestv[i];
        int ix = besti[i];
#pragma unroll
        for (int off = 8; off >= 1; off >>= 1) {
            float ov = __shfl_down_sync(0xffffffffu, v, off, 16);
            int oi = __shfl_down_sync(0xffffffffu, ix, off, 16);
            if (ov < v || (ov == v && oi < ix)) { v = ov; ix = oi; }
        }
        if (tx == 0) {
            int mloc = ty * 4 + i;
            s_ind[mloc] = ix;
            out[OUT_INDS + m0 + mloc] = (float)ix;
        }
    }
    __syncthreads();

    // Gather quantized, straight-through value, loss partial
    float lsum = 0.f;
    for (int e = tid; e < 64 * DDIM; e += 256) {
        int r = e >> 7;
        int d = e & 127;
        float l = Ls[d][r];
        float q = cb[s_ind[r] * DDIM + d];
        float qmL = q - l;
        float qst = l + qmL;          // matches jax quantized_st fp ordering
        int m = m0 + r;
        out[OUT_Q + m * DDIM + d] = qst;
        gq[m * DDIM + d] = qst;
        lsum += qmL * qmL;
    }
    s_red[tid] = lsum;
    __syncthreads();
    for (int s = 128; s > 0; s >>= 1) {
        if (tid < s) s_red[tid] += s_red[tid + s];
        __syncthreads();
    }
    if (tid == 0) part[blockIdx.x] = s_red[0];
}

// ---------------------------------------------------------------------------
// Decoder layer 3: recons = tanh(d2 @ Wd3 + bd3), Wd3 is [H,6]. Warp per row.
// ---------------------------------------------------------------------------
__global__ void k_dec3(const float* __restrict__ d2, const float* __restrict__ Wd3,
                       const float* __restrict__ bd3, float* __restrict__ out)
{
    int warp = (blockIdx.x * blockDim.x + threadIdx.x) >> 5;   // row n
    int lane = threadIdx.x & 31;
    const float* row = d2 + warp * HDIM;
    float a0 = 0.f, a1 = 0.f, a2 = 0.f, a3 = 0.f, a4 = 0.f, a5 = 0.f;
#pragma unroll 4
    for (int k = lane; k < HDIM; k += 32) {
        float v = row[k];
        const float* w = Wd3 + k * ADIM;
        a0 += v * w[0]; a1 += v * w[1]; a2 += v * w[2];
        a3 += v * w[3]; a4 += v * w[4]; a5 += v * w[5];
    }
#pragma unroll
    for (int off = 16; off; off >>= 1) {
        a0 += __shfl_xor_sync(0xffffffffu, a0, off);
        a1 += __shfl_xor_sync(0xffffffffu, a1, off);
        a2 += __shfl_xor_sync(0xffffffffu, a2, off);
        a3 += __shfl_xor_sync(0xffffffffu, a3, off);
        a4 += __shfl_xor_sync(0xffffffffu, a4, off);
        a5 += __shfl_xor_sync(0xffffffffu, a5, off);
    }
    if (lane == 0) {
        float* o = out + OUT_REC + warp * ADIM;
        o[0] = tanhf(a0 + bd3[0]);
        o[1] = tanhf(a1 + bd3[1]);
        o[2] = tanhf(a2 + bd3[2]);
        o[3] = tanhf(a3 + bd3[3]);
        o[4] = tanhf(a4 + bd3[4]);
        o[5] = tanhf(a5 + bd3[5]);
    }
}

// ---------------------------------------------------------------------------
// Final loss reduction (deterministic fixed-order tree)
// ---------------------------------------------------------------------------
__global__ void k_loss(const float* __restrict__ part, float* __restrict__ out)
{
    __shared__ float s[256];
    int tid = threadIdx.x;
    s[tid] = part[tid] + part[tid + 256];
    __syncthreads();
    for (int st = 128; st > 0; st >>= 1) {
        if (tid < st) s[tid] += s[tid + st];
        __syncthreads();
    }
    if (tid == 0)
        out[OUT_LOSS] = 1.25f * s[0] / (float)(NTOK * DDIM);
}

// ---------------------------------------------------------------------------
extern "C" void kernel_launch(void* const* d_in, const int* in_sizes, int n_in,
                              void* d_out, int out_size)
{
    const float* action = (const float*)d_in[0];
    const float* W1   = (const float*)d_in[1];
    const float* b1   = (const float*)d_in[2];
    const float* W2   = (const float*)d_in[3];
    const float* b2   = (const float*)d_in[4];
    const float* Wmu  = (const float*)d_in[5];
    const float* bmu  = (const float*)d_in[6];
    const float* cb   = (const float*)d_in[7];
    const float* Wd1  = (const float*)d_in[8];
    const float* bd1  = (const float*)d_in[9];
    const float* Wd2  = (const float*)d_in[10];
    const float* bd2  = (const float*)d_in[11];
    const float* Wd3  = (const float*)d_in[12];
    const float* bd3  = (const float*)d_in[13];
    float* out = (float*)d_out;

    float *p_h1, *p_h2, *p_lat, *p_q, *p_ln, *p_cn, *p_part;
    cudaGetSymbolAddress((void**)&p_h1, g_h1);
    cudaGetSymbolAddress((void**)&p_h2, g_h2);
    cudaGetSymbolAddress((void**)&p_lat, g_lat);
    cudaGetSymbolAddress((void**)&p_q, g_q);
    cudaGetSymbolAddress((void**)&p_ln, g_ln);
    cudaGetSymbolAddress((void**)&p_cn, g_cn);
    cudaGetSymbolAddress((void**)&p_part, g_part);

    // codebook norms
    k_cnorm<<<KCB / 8, 256>>>(cb, p_cn);
    // encoder
    k_enc1<<<(NTOK * HDIM) / 256, 256>>>(action, W1, b1, p_h1);
    sgemm<1><<<dim3(HDIM / 128, NTOK / 128), 256>>>(p_h1, W2, b2, p_h2, NTOK, HDIM, HDIM);
    sgemm<0><<<dim3(DDIM / 128, NTOK / 128), 256>>>(p_h2, Wmu, bmu, p_lat, NTOK, DDIM, HDIM);
    // row norms of latents (XLA-order reduction)
    k_rownorm<<<NTOK / 8, 256>>>(p_lat, p_ln);
    // vector quantization (writes inds + quantized_st to out, g_q scratch, loss partials)
    k_vq<<<VQ_BLOCKS, 256>>>(p_lat, cb, p_cn, p_ln, out, p_q, p_part);
    // decoder
    sgemm<1><<<dim3(HDIM / 128, NTOK / 128), 256>>>(p_q, Wd1, bd1, p_h1, NTOK, HDIM, DDIM);
    sgemm<1><<<dim3(HDIM / 128, NTOK / 128), 256>>>(p_h1, Wd2, bd2, p_h2, NTOK, HDIM, HDIM);
    k_dec3<<<NTOK / 8, 256>>>(p_h2, Wd3, bd3, out);
    // scalar loss
    k_loss<<<1, 256>>>(p_part, out);
}